// round 15
// baseline (speedup 1.0000x reference)
#include <cuda_runtime.h>
#include <cuda_fp16.h>
#include <cstdint>

#define NROWS 200000
#define CIN1  64
#define COUT  128
#define NTAPS 27
#define EPSBN 1e-5f
#define NPART 782    // ceil(NROWS/256) == conv grid size

// ---------------- scratch (device globals; no allocation allowed) ----------
__device__ float g_hpre[(size_t)NROWS * COUT];    // conv1 pre-BN
__device__ float g_respre[(size_t)NROWS * COUT];  // conv2 pre-BN
__device__ float g_skippre[(size_t)NROWS * COUT]; // skip pre-BN
__device__ __half g_fh[(size_t)NROWS * CIN1];
__device__ __half g_hh[(size_t)NROWS * COUT];
__device__ __half g_w1h[(size_t)NTAPS * COUT * CIN1];  // [tap][n][k]
__device__ __half g_w2h[(size_t)NTAPS * COUT * COUT];
__device__ __half g_wskh[(size_t)COUT * CIN1];
__device__ float g_psum[2][NPART][COUT];   // fused per-CTA stats partials
__device__ float g_psq[2][NPART][COUT];
__device__ float g_inv[3][COUT];    // g * rsqrt(var+eps)
__device__ float g_shift[3][COUT];  // b - mean*inv

// ---------------- PTX helpers (baseline features only) -----------------------
__device__ __forceinline__ uint32_t smem_u32(const void* p) {
    uint32_t a;
    asm("{ .reg .u64 t; cvta.to.shared.u64 t, %1; cvt.u32.u64 %0, t; }"
        : "=r"(a) : "l"(p));
    return a;
}
__device__ __forceinline__ void cpasync16(uint32_t dst, const void* src, int srcsize) {
    asm volatile("cp.async.cg.shared.global [%0], [%1], 16, %2;"
                 :: "r"(dst), "l"(src), "r"(srcsize));
}
__device__ __forceinline__ void cpcommit() {
    asm volatile("cp.async.commit_group;");
}
__device__ __forceinline__ void ldm4(uint32_t* r, uint32_t addr) {
    asm volatile("ldmatrix.sync.aligned.m8n8.x4.shared.b16 {%0,%1,%2,%3}, [%4];"
                 : "=r"(r[0]), "=r"(r[1]), "=r"(r[2]), "=r"(r[3]) : "r"(addr));
}
__device__ __forceinline__ void mma16816(float* d, const uint32_t* a, const uint32_t* b) {
    asm volatile(
        "mma.sync.aligned.m16n8k16.row.col.f32.f16.f16.f32 "
        "{%0,%1,%2,%3},{%4,%5,%6,%7},{%8,%9},{%0,%1,%2,%3};"
        : "+f"(d[0]), "+f"(d[1]), "+f"(d[2]), "+f"(d[3])
        : "r"(a[0]), "r"(a[1]), "r"(a[2]), "r"(a[3]), "r"(b[0]), "r"(b[1]));
}

// smem: X tile 256 rows x 64B (16 KB) + W tile 128 rows x 64B (8 KB), XOR swizzle.
#define XTILE_B 16384
#define WTILE_B 8192
#define STAGE_B (XTILE_B + WTILE_B)    // 24 KB
#define NSTAGE 4
#define X_OFF 0
#define W_OFF XTILE_B

__device__ __forceinline__ uint32_t sw_off(int row, int bytecol) {
    const int ch = bytecol >> 4;
    return (uint32_t)(row * 64) + (((uint32_t)(ch ^ ((row >> 1) & 3))) << 4);
}

// ---------------- HMMA gathered multi-tap GEMM (pure fp16, fp32 acc) ---------
// CTA tile 256x128, 8 warps (4M x 2N), warp tile 64x64 -> halves LDSM per MMA.
// Pipeline: wait(s) -> barrier -> issue loads(s+3) -> compute(s).
template <bool GATHER>
__global__ __launch_bounds__(256, 1)
void mma_conv_kernel(const __half* __restrict__ X,
                     const int* __restrict__ nbr,
                     const __half* __restrict__ W,
                     float* __restrict__ Y, int ntaps, int xk, int cptsh,
                     int pslot) {
    extern __shared__ char smem[];
    const uint32_t sb = smem_u32(smem);
    const int tid = threadIdx.x;
    const int wid = tid >> 5;
    const int lid = tid & 31;
    const int row0 = blockIdx.x * 256;
    const int kmask = (1 << cptsh) - 1;
    const int nsub = ntaps << cptsh;

    const int wm = (wid & 3) * 64;      // warp M offset (0..192)
    const int wn = (wid >> 2) * 64;     // warp N offset (0 or 64)

    float acc[4][8][4];
#pragma unroll
    for (int i = 0; i < 4; i++)
#pragma unroll
        for (int j = 0; j < 8; j++)
#pragma unroll
            for (int q = 0; q < 4; q++) acc[i][j][q] = 0.f;

    auto src_of = [&](int s) -> int {
        const int grow = row0 + tid;
        if (!GATHER) return grow;
        const int tap = s >> cptsh;
        return (grow < NROWS) ? __ldg(nbr + (size_t)tap * NROWS + grow) : NROWS;
    };

    // loads: each thread owns X row 'tid' (4 chunks) + W row 'tid&127' (2 chunks)
    const int wrow = tid & 127;
    const int wcb = (tid >> 7) * 2;     // W chunk base 0 or 2
    auto load_stage = [&](int s, int src) {
        const int buf = s & (NSTAGE - 1);
        const int kc = s & kmask;
        const uint32_t st = sb + buf * STAGE_B;
        const bool val = (unsigned)src < (unsigned)NROWS;
        const int srow = val ? src : 0;
        const int sz = val ? 16 : 0;
        const __half* xp = X + (size_t)srow * xk + kc * 32;
        const int tap = s >> cptsh;
        const __half* wp = W + ((size_t)tap * 128 + wrow) * xk + kc * 32;
        const int xsel = (tid >> 1) & 3;
        const uint32_t xb = st + X_OFF + tid * 64;
#pragma unroll
        for (int c = 0; c < 4; c++)
            cpasync16(xb + (((uint32_t)(c ^ xsel)) << 4), xp + c * 8, sz);
        const int wsel = (wrow >> 1) & 3;
        const uint32_t wb = st + W_OFF + wrow * 64;
#pragma unroll
        for (int c = 0; c < 2; c++) {
            const int c2 = wcb + c;
            cpasync16(wb + (((uint32_t)(c2 ^ wsel)) << 4), wp + c2 * 8, 16);
        }
    };

    // ---- prologue: 3 stages in flight
    load_stage(0, src_of(0));
    cpcommit();
    if (nsub > 1) { load_stage(1, src_of(1)); cpcommit(); }
    if (nsub > 2) { load_stage(2, src_of(2)); cpcommit(); }
    int src3 = (nsub > 3) ? src_of(3) : 0;

    // ---- precomputed fragment smem offsets
    const int b_nrow = (lid & 7) + ((lid >> 4) << 3);
    const int b_kof = ((lid >> 3) & 1) * 16;
    const int a_row = lid & 15;
    const int a_kof = (lid >> 4) * 16;
    uint32_t boff[2][4], aoff[2][4];
#pragma unroll
    for (int kh = 0; kh < 2; kh++) {
#pragma unroll
        for (int half = 0; half < 4; half++)
            boff[kh][half] = W_OFF + sw_off(wn + half * 16 + b_nrow, kh * 32 + b_kof);
#pragma unroll
        for (int mi = 0; mi < 4; mi++)
            aoff[kh][mi] = X_OFF + sw_off(wm + mi * 16 + a_row, kh * 32 + a_kof);
    }

    for (int s = 0; s < nsub; s++) {
        if (s + 2 < nsub) {
            asm volatile("cp.async.wait_group 2;");
        } else if (s + 1 < nsub) {
            asm volatile("cp.async.wait_group 1;");
        } else {
            asm volatile("cp.async.wait_group 0;");
        }
        __syncthreads();   // single barrier per stage

        if (s + 3 < nsub) {
            load_stage(s + 3, src3);
            cpcommit();
            src3 = (s + 4 < nsub) ? src_of(s + 4) : 0;
        }

        const uint32_t st = sb + (s & (NSTAGE - 1)) * STAGE_B;
#pragma unroll
        for (int kh = 0; kh < 2; kh++) {
            uint32_t bh[8][2];
#pragma unroll
            for (int half = 0; half < 4; half++) {
                const uint32_t wa = st + boff[kh][half];
                uint32_t rg[4];
                ldm4(rg, wa);
                bh[half * 2][0] = rg[0]; bh[half * 2][1] = rg[1];
                bh[half * 2 + 1][0] = rg[2]; bh[half * 2 + 1][1] = rg[3];
            }
#pragma unroll
            for (int mi = 0; mi < 4; mi++) {
                const uint32_t aa = st + aoff[kh][mi];
                uint32_t ah[4];
                ldm4(ah, aa);
#pragma unroll
                for (int ni = 0; ni < 8; ni++)
                    mma16816(acc[mi][ni], ah, bh[ni]);
            }
        }
    }

    // ---- epilogue 1: write fp32 tile
#pragma unroll
    for (int mi = 0; mi < 4; mi++) {
        const int m0 = row0 + wm + mi * 16 + (lid >> 2);
#pragma unroll
        for (int ni = 0; ni < 8; ni++) {
            const int col = wn + ni * 8 + 2 * (lid & 3);
            if (m0 < NROWS)
                *(float2*)(Y + (size_t)m0 * 128 + col) =
                    make_float2(acc[mi][ni][0], acc[mi][ni][1]);
            if (m0 + 8 < NROWS)
                *(float2*)(Y + (size_t)(m0 + 8) * 128 + col) =
                    make_float2(acc[mi][ni][2], acc[mi][ni][3]);
        }
    }

    // ---- epilogue 2: fused column stats (rows beyond NROWS contribute 0)
    float ts[16], tq[16];
#pragma unroll
    for (int ni = 0; ni < 8; ni++)
#pragma unroll
        for (int j = 0; j < 2; j++) {
            float s = 0.f, q = 0.f;
#pragma unroll
            for (int mi = 0; mi < 4; mi++) {
                float v0 = acc[mi][ni][j];
                float v1 = acc[mi][ni][j + 2];
                s += v0 + v1;
                q += v0 * v0 + v1 * v1;
            }
            ts[ni * 2 + j] = s;
            tq[ni * 2 + j] = q;
        }
#pragma unroll
    for (int o = 16; o >= 4; o >>= 1)
#pragma unroll
        for (int i = 0; i < 16; i++) {
            ts[i] += __shfl_down_sync(0xffffffffu, ts[i], o);
            tq[i] += __shfl_down_sync(0xffffffffu, tq[i], o);
        }
    __syncthreads();   // all compute done; stage smem free for reuse
    float* ss = (float*)smem;          // [8][64]
    float* sq = ss + 512;
    if (lid < 4) {
#pragma unroll
        for (int ni = 0; ni < 8; ni++)
#pragma unroll
            for (int j = 0; j < 2; j++) {
                const int cl = ni * 8 + 2 * lid + j;
                ss[wid * 64 + cl] = ts[ni * 2 + j];
                sq[wid * 64 + cl] = tq[ni * 2 + j];
            }
    }
    __syncthreads();
    if (tid < COUT) {
        const int g = tid >> 6;        // which N-half -> warp group
        const int c = tid & 63;
        float s = 0.f, q = 0.f;
#pragma unroll
        for (int m = 0; m < 4; m++) {
            s += ss[(g * 4 + m) * 64 + c];
            q += sq[(g * 4 + m) * 64 + c];
        }
        g_psum[pslot][blockIdx.x][tid] = s;
        g_psq[pslot][blockIdx.x][tid]  = q;
    }
}

// ---------------- prep: W transpose + fp16 convert ----------------------------
__global__ void wconv_kernel(const float* __restrict__ W,
                             __half* __restrict__ hi, int taps, int K) {
    int i = blockIdx.x * blockDim.x + threadIdx.x;
    int total = taps * 128 * K;
    if (i >= total) return;
    int kk = i % K;
    int t2 = i / K;
    int n = t2 & 127;
    int tap = t2 >> 7;
    float v = __ldg(W + ((size_t)tap * K + kk) * 128 + n);
    hi[i] = __float2half_rn(v);
}

// ---------------- prep: feats fp16 convert (vector) ---------------------------
__global__ void xconv_kernel(const float4* __restrict__ X,
                             uint2* __restrict__ hi, long long n4) {
    long long i = (long long)blockIdx.x * blockDim.x + threadIdx.x;
    if (i >= n4) return;
    float4 v = X[i];
    __half2 h01 = __halves2half2(__float2half_rn(v.x), __float2half_rn(v.y));
    __half2 h23 = __halves2half2(__float2half_rn(v.z), __float2half_rn(v.w));
    hi[i] = make_uint2(*(uint32_t*)&h01, *(uint32_t*)&h23);
}

// ---------------- BN finalize from fused partials (parallel) ------------------
__device__ __forceinline__ void finalize_body(const float* g, const float* b,
                                              int slot, int pslot) {
    __shared__ float ss[8][COUT];
    __shared__ float sq[8][COUT];
    const int col = threadIdx.x & (COUT - 1);
    const int chunk = threadIdx.x >> 7;     // 0..7
    const int beg = chunk * 98;
    const int end = (chunk == 7) ? NPART : (beg + 98);
    float s0 = 0.f, s1 = 0.f, q0 = 0.f, q1 = 0.f;
    int i = beg;
    for (; i + 1 < end; i += 2) {
        s0 += g_psum[pslot][i][col];
        q0 += g_psq[pslot][i][col];
        s1 += g_psum[pslot][i + 1][col];
        q1 += g_psq[pslot][i + 1][col];
    }
    for (; i < end; i++) {
        s0 += g_psum[pslot][i][col];
        q0 += g_psq[pslot][i][col];
    }
    ss[chunk][col] = s0 + s1;
    sq[chunk][col] = q0 + q1;
    __syncthreads();
    if (chunk == 0) {
        float s = 0.f, q = 0.f;
#pragma unroll
        for (int c = 0; c < 8; c++) { s += ss[c][col]; q += sq[c][col]; }
        float mean = s * (1.0f / NROWS);
        float var = q * (1.0f / NROWS) - mean * mean;
        float inv = g[col] * rsqrtf(var + EPSBN);
        g_inv[slot][col] = inv;
        g_shift[slot][col] = b[col] - mean * inv;
    }
}

__global__ void finalize_kernel(const float* __restrict__ g,
                                const float* __restrict__ b, int slot, int pslot) {
    finalize_body(g, b, slot, pslot);
}

// fused: block 0 -> BN2 (slot 1, pslot 0); block 1 -> BNskip (slot 2, pslot 1)
__global__ void finalize2_kernel(const float* __restrict__ g2,
                                 const float* __restrict__ b2,
                                 const float* __restrict__ gsk,
                                 const float* __restrict__ bsk) {
    if (blockIdx.x == 0) finalize_body(g2, b2, 1, 0);
    else                 finalize_body(gsk, bsk, 2, 1);
}

// ---------------- BN apply (slot 0) fused with fp16 convert -------------------
__global__ void bnconv_kernel(const float4* __restrict__ X,
                              uint2* __restrict__ hi) {
    long long i = (long long)blockIdx.x * blockDim.x + threadIdx.x;
    const long long total = (long long)NROWS * COUT / 4;
    if (i >= total) return;
    int c4 = (int)(i & (COUT / 4 - 1)) * 4;
    float4 v = X[i];
    v.x = v.x * g_inv[0][c4 + 0] + g_shift[0][c4 + 0];
    v.y = v.y * g_inv[0][c4 + 1] + g_shift[0][c4 + 1];
    v.z = v.z * g_inv[0][c4 + 2] + g_shift[0][c4 + 2];
    v.w = v.w * g_inv[0][c4 + 3] + g_shift[0][c4 + 3];
    __half2 h01 = __halves2half2(__float2half_rn(v.x), __float2half_rn(v.y));
    __half2 h23 = __halves2half2(__float2half_rn(v.z), __float2half_rn(v.w));
    hi[i] = make_uint2(*(uint32_t*)&h01, *(uint32_t*)&h23);
}

// ---------------- final: relu(bn(res) + bn(skip)) ----------------------------
__global__ void final_kernel(float4* __restrict__ out) {
    long long i = (long long)blockIdx.x * blockDim.x + threadIdx.x;
    const long long total = (long long)NROWS * COUT / 4;
    if (i >= total) return;
    int c4 = (int)(i & (COUT / 4 - 1)) * 4;
    const float4 r = ((const float4*)g_respre)[i];
    const float4 s = ((const float4*)g_skippre)[i];
    float4 o;
    o.x = fmaxf(r.x * g_inv[1][c4 + 0] + g_shift[1][c4 + 0] +
                s.x * g_inv[2][c4 + 0] + g_shift[2][c4 + 0], 0.f);
    o.y = fmaxf(r.y * g_inv[1][c4 + 1] + g_shift[1][c4 + 1] +
                s.y * g_inv[2][c4 + 1] + g_shift[2][c4 + 1], 0.f);
    o.z = fmaxf(r.z * g_inv[1][c4 + 2] + g_shift[1][c4 + 2] +
                s.z * g_inv[2][c4 + 2] + g_shift[2][c4 + 2], 0.f);
    o.w = fmaxf(r.w * g_inv[1][c4 + 3] + g_shift[1][c4 + 3] +
                s.w * g_inv[2][c4 + 3] + g_shift[2][c4 + 3], 0.f);
    out[i] = o;
}

// ---------------- launch ------------------------------------------------------
extern "C" void kernel_launch(void* const* d_in, const int* in_sizes, int n_in,
                              void* d_out, int out_size) {
    const float* feats = (const float*)d_in[0];
    const int*   nbr   = (const int*)d_in[1];
    const float* W1    = (const float*)d_in[2];
    const float* g1    = (const float*)d_in[3];
    const float* b1    = (const float*)d_in[4];
    const float* W2    = (const float*)d_in[5];
    const float* g2    = (const float*)d_in[6];
    const float* b2    = (const float*)d_in[7];
    const float* Wsk   = (const float*)d_in[8];
    const float* gsk   = (const float*)d_in[9];
    const float* bsk   = (const float*)d_in[10];
    float* out = (float*)d_out;

    float *hpre, *respre, *skippre;
    __half *fh, *hh, *w1h, *w2h, *wskh;
    cudaGetSymbolAddress((void**)&hpre, g_hpre);
    cudaGetSymbolAddress((void**)&respre, g_respre);
    cudaGetSymbolAddress((void**)&skippre, g_skippre);
    cudaGetSymbolAddress((void**)&fh, g_fh);
    cudaGetSymbolAddress((void**)&hh, g_hh);
    cudaGetSymbolAddress((void**)&w1h, g_w1h);
    cudaGetSymbolAddress((void**)&w2h, g_w2h);
    cudaGetSymbolAddress((void**)&wskh, g_wskh);

    const int SMEM_BYTES = NSTAGE * STAGE_B;  // 98304
    cudaFuncSetAttribute(mma_conv_kernel<true>,
                         cudaFuncAttributeMaxDynamicSharedMemorySize, SMEM_BYTES);
    cudaFuncSetAttribute(mma_conv_kernel<false>,
                         cudaFuncAttributeMaxDynamicSharedMemorySize, SMEM_BYTES);

    const int grid = NPART;  // 782
    const long long total4 = (long long)NROWS * COUT / 4;
    const int egrid = (int)((total4 + 255) / 256);
    const long long f4 = (long long)NROWS * CIN1 / 4;

    // ---- prep (ordered so launch index 3 == conv1, which ncu captures)
    wconv_kernel<<<(NTAPS * 128 * CIN1 + 255) / 256, 256>>>(W1, w1h, NTAPS, CIN1);
    xconv_kernel<<<(int)((f4 + 255) / 256), 256>>>((const float4*)feats,
                                                   (uint2*)fh, f4);
    wconv_kernel<<<(NTAPS * 128 * COUT + 255) / 256, 256>>>(W2, w2h, NTAPS, COUT);

    // ---- conv1: 27 taps, K=64  (launch index 3 -> profiled); stats -> pslot 0
    mma_conv_kernel<true><<<grid, 256, SMEM_BYTES>>>(fh, nbr, w1h, hpre,
                                                     NTAPS, CIN1, 1, 0);

    // ---- skip branch; stats -> pslot 1
    wconv_kernel<<<(128 * CIN1 + 255) / 256, 256>>>(Wsk, wskh, 1, CIN1);
    mma_conv_kernel<false><<<grid, 256, SMEM_BYTES>>>(fh, nullptr, wskh, skippre,
                                                      1, CIN1, 1, 1);

    // ---- BN1 finalize (parallel) + fused apply+convert
    finalize_kernel<<<1, 1024>>>(g1, b1, 0, 0);
    bnconv_kernel<<<egrid, 256>>>((const float4*)hpre, (uint2*)hh);
    // ---- conv2: 27 taps, K=128; stats -> pslot 0
    mma_conv_kernel<true><<<grid, 256, SMEM_BYTES>>>(hh, nbr, w2h, respre,
                                                     NTAPS, COUT, 2, 0);
    // ---- BN2 + BNskip finalize (fused into one launch)
    finalize2_kernel<<<2, 1024>>>(g2, b2, gsk, bsk);
    // ---- out = relu(bn(res) + bn(skip))
    final_kernel<<<egrid, 256>>>((float4*)out);
}

// round 16
// speedup vs baseline: 1.3363x; 1.3363x over previous
#include <cuda_runtime.h>
#include <cuda_fp16.h>
#include <cstdint>

#define NROWS 200000
#define CIN1  64
#define COUT  128
#define NTAPS 27
#define EPSBN 1e-5f
#define NPART 1563   // ceil(NROWS/128) == conv grid size

// ---------------- scratch (device globals; no allocation allowed) ----------
__device__ __half g_hpre[(size_t)NROWS * COUT];    // conv1 pre-BN (fp16)
__device__ __half g_respre[(size_t)NROWS * COUT];  // conv2 pre-BN (fp16)
__device__ __half g_skippre[(size_t)NROWS * COUT]; // skip pre-BN (fp16)
__device__ __half g_fh[(size_t)NROWS * CIN1];
__device__ __half g_hh[(size_t)NROWS * COUT];
__device__ __half g_w1h[(size_t)NTAPS * COUT * CIN1];  // [tap][n][k]
__device__ __half g_w2h[(size_t)NTAPS * COUT * COUT];
__device__ __half g_wskh[(size_t)COUT * CIN1];
__device__ float g_psum[2][NPART][COUT];   // fused per-CTA stats partials
__device__ float g_psq[2][NPART][COUT];
__device__ float g_inv[3][COUT];    // g * rsqrt(var+eps)
__device__ float g_shift[3][COUT];  // b - mean*inv

// ---------------- PTX helpers (baseline features only) -----------------------
__device__ __forceinline__ uint32_t smem_u32(const void* p) {
    uint32_t a;
    asm("{ .reg .u64 t; cvta.to.shared.u64 t, %1; cvt.u32.u64 %0, t; }"
        : "=r"(a) : "l"(p));
    return a;
}
__device__ __forceinline__ void cpasync16(uint32_t dst, const void* src, int srcsize) {
    asm volatile("cp.async.cg.shared.global [%0], [%1], 16, %2;"
                 :: "r"(dst), "l"(src), "r"(srcsize));
}
__device__ __forceinline__ void cpcommit() {
    asm volatile("cp.async.commit_group;");
}
__device__ __forceinline__ void ldm4(uint32_t* r, uint32_t addr) {
    asm volatile("ldmatrix.sync.aligned.m8n8.x4.shared.b16 {%0,%1,%2,%3}, [%4];"
                 : "=r"(r[0]), "=r"(r[1]), "=r"(r[2]), "=r"(r[3]) : "r"(addr));
}
__device__ __forceinline__ void mma16816(float* d, const uint32_t* a, const uint32_t* b) {
    asm volatile(
        "mma.sync.aligned.m16n8k16.row.col.f32.f16.f16.f32 "
        "{%0,%1,%2,%3},{%4,%5,%6,%7},{%8,%9},{%0,%1,%2,%3};"
        : "+f"(d[0]), "+f"(d[1]), "+f"(d[2]), "+f"(d[3])
        : "r"(a[0]), "r"(a[1]), "r"(a[2]), "r"(a[3]), "r"(b[0]), "r"(b[1]));
}

// smem tile geometry: 128 rows x 64B (32 fp16), XOR swizzle, no padding.
#define TILE_B 8192
#define NSTAGE 4
#define STAGE_B (2 * TILE_B)         // X, W = 16 KB
#define X_OFF 0
#define W_OFF TILE_B

__device__ __forceinline__ uint32_t sw_off(int row, int bytecol) {
    const int ch = bytecol >> 4;
    return (uint32_t)(row * 64) + (((uint32_t)(ch ^ ((row >> 1) & 3))) << 4);
}

// ---------------- HMMA gathered multi-tap GEMM (pure fp16, fp32 acc) ---------
// Round-14 proven config: 128x128 CTA tile, 8 warps 2Mx4N, 2 CTAs/SM.
// Pipeline: wait(s) -> barrier -> issue loads(s+3) -> compute(s).
// Output Y stored as fp16 (stats remain exact from fp32 accumulators).
template <bool GATHER>
__global__ __launch_bounds__(256, 2)
void mma_conv_kernel(const __half* __restrict__ X,
                     const int* __restrict__ nbr,
                     const __half* __restrict__ W,
                     __half* __restrict__ Y, int ntaps, int xk, int cptsh,
                     int pslot) {
    extern __shared__ char smem[];
    const uint32_t sb = smem_u32(smem);
    const int tid = threadIdx.x;
    const int wid = tid >> 5;
    const int lid = tid & 31;
    const int row0 = blockIdx.x * 128;
    const int kmask = (1 << cptsh) - 1;
    const int nsub = ntaps << cptsh;

    const int wm = (wid & 1) * 64;      // warp M offset
    const int wn = (wid >> 1) * 32;     // warp N offset

    const int lr = tid >> 1;            // load row 0..127
    const int lc = (tid & 1) * 2;       // chunk pair 0/2

    float acc[4][4][4];
#pragma unroll
    for (int i = 0; i < 4; i++)
#pragma unroll
        for (int j = 0; j < 4; j++)
#pragma unroll
            for (int q = 0; q < 4; q++) acc[i][j][q] = 0.f;

    auto src_of = [&](int s) -> int {
        const int grow = row0 + lr;
        if (!GATHER) return grow;
        const int tap = s >> cptsh;
        return (grow < NROWS) ? __ldg(nbr + (size_t)tap * NROWS + grow) : NROWS;
    };

    auto load_stage = [&](int s, int src) {
        const int buf = s & (NSTAGE - 1);
        const int kc = s & kmask;
        const uint32_t st = sb + buf * STAGE_B;
        const bool val = (unsigned)src < (unsigned)NROWS;
        const int srow = val ? src : 0;
        const int sz = val ? 16 : 0;
        const __half* xp = X + (size_t)srow * xk + kc * 32;
        const int tap = s >> cptsh;
        const __half* wp = W + ((size_t)tap * 128 + lr) * xk + kc * 32;
        const int sel = (lr >> 1) & 3;
        const uint32_t rbase = st + lr * 64;
#pragma unroll
        for (int c = 0; c < 2; c++) {
            const uint32_t d = rbase + (((uint32_t)((lc + c) ^ sel)) << 4);
            cpasync16(d + X_OFF, xp + (lc + c) * 8, sz);
            cpasync16(d + W_OFF, wp + (lc + c) * 8, 16);
        }
    };

    // ---- prologue: up to 3 stages in flight
    load_stage(0, src_of(0));
    cpcommit();
    if (nsub > 1) { load_stage(1, src_of(1)); cpcommit(); }
    if (nsub > 2) { load_stage(2, src_of(2)); cpcommit(); }
    int src3 = (nsub > 3) ? src_of(3) : 0;

    // ---- precomputed fragment smem offsets (swizzle hoisted out of mainloop)
    const int b_nrow = (lid & 7) + ((lid >> 4) << 3);
    const int b_kof = ((lid >> 3) & 1) * 16;
    const int a_row = lid & 15;
    const int a_kof = (lid >> 4) * 16;
    uint32_t boff[2][2], aoff[2][4];
#pragma unroll
    for (int kh = 0; kh < 2; kh++) {
#pragma unroll
        for (int half = 0; half < 2; half++)
            boff[kh][half] = W_OFF + sw_off(wn + half * 16 + b_nrow, kh * 32 + b_kof);
#pragma unroll
        for (int mi = 0; mi < 4; mi++)
            aoff[kh][mi] = X_OFF + sw_off(wm + mi * 16 + a_row, kh * 32 + a_kof);
    }

    for (int s = 0; s < nsub; s++) {
        if (s + 2 < nsub) {
            asm volatile("cp.async.wait_group 2;");
        } else if (s + 1 < nsub) {
            asm volatile("cp.async.wait_group 1;");
        } else {
            asm volatile("cp.async.wait_group 0;");
        }
        __syncthreads();   // single barrier per stage

        if (s + 3 < nsub) {
            load_stage(s + 3, src3);
            cpcommit();
            src3 = (s + 4 < nsub) ? src_of(s + 4) : 0;
        }

        const uint32_t st = sb + (s & (NSTAGE - 1)) * STAGE_B;
#pragma unroll
        for (int kh = 0; kh < 2; kh++) {
            uint32_t bh[4][2];
#pragma unroll
            for (int half = 0; half < 2; half++) {
                const uint32_t wa = st + boff[kh][half];
                uint32_t rg[4];
                ldm4(rg, wa);
                bh[half * 2][0] = rg[0]; bh[half * 2][1] = rg[1];
                bh[half * 2 + 1][0] = rg[2]; bh[half * 2 + 1][1] = rg[3];
            }
#pragma unroll
            for (int mi = 0; mi < 4; mi++) {
                const uint32_t aa = st + aoff[kh][mi];
                uint32_t ah[4];
                ldm4(ah, aa);
#pragma unroll
                for (int ni = 0; ni < 4; ni++)
                    mma16816(acc[mi][ni], ah, bh[ni]);
            }
        }
    }

    // ---- epilogue 1: write fp16 tile (stats below stay fp32-exact)
#pragma unroll
    for (int mi = 0; mi < 4; mi++) {
        const int m0 = row0 + wm + mi * 16 + (lid >> 2);
#pragma unroll
        for (int ni = 0; ni < 4; ni++) {
            const int col = wn + ni * 8 + 2 * (lid & 3);
            __half2 p01 = __floats2half2_rn(acc[mi][ni][0], acc[mi][ni][1]);
            __half2 p23 = __floats2half2_rn(acc[mi][ni][2], acc[mi][ni][3]);
            if (m0 < NROWS)
                *(__half2*)(Y + (size_t)m0 * 128 + col) = p01;
            if (m0 + 8 < NROWS)
                *(__half2*)(Y + (size_t)(m0 + 8) * 128 + col) = p23;
        }
    }

    // ---- epilogue 2: fused column stats (rows beyond NROWS contribute 0)
    float ts[8], tq[8];
#pragma unroll
    for (int ni = 0; ni < 4; ni++)
#pragma unroll
        for (int j = 0; j < 2; j++) {
            float s = 0.f, q = 0.f;
#pragma unroll
            for (int mi = 0; mi < 4; mi++) {
                float v0 = acc[mi][ni][j];
                float v1 = acc[mi][ni][j + 2];
                s += v0 + v1;
                q += v0 * v0 + v1 * v1;
            }
            ts[ni * 2 + j] = s;
            tq[ni * 2 + j] = q;
        }
#pragma unroll
    for (int o = 16; o >= 4; o >>= 1)
#pragma unroll
        for (int i = 0; i < 8; i++) {
            ts[i] += __shfl_down_sync(0xffffffffu, ts[i], o);
            tq[i] += __shfl_down_sync(0xffffffffu, tq[i], o);
        }
    __syncthreads();   // all compute done; stage smem free for reuse
    float* ss = (float*)smem;          // [8][32]
    float* sq = ss + 256;
    if (lid < 4) {
#pragma unroll
        for (int ni = 0; ni < 4; ni++)
#pragma unroll
            for (int j = 0; j < 2; j++) {
                const int cl = ni * 8 + 2 * lid + j;
                ss[wid * 32 + cl] = ts[ni * 2 + j];
                sq[wid * 32 + cl] = tq[ni * 2 + j];
            }
    }
    __syncthreads();
    if (tid < COUT) {
        const int w0 = (tid >> 5) * 2;
        const int c = tid & 31;
        g_psum[pslot][blockIdx.x][tid] = ss[w0 * 32 + c] + ss[w0 * 32 + 32 + c];
        g_psq[pslot][blockIdx.x][tid]  = sq[w0 * 32 + c] + sq[w0 * 32 + 32 + c];
    }
}

// ---------------- prep: W transpose + fp16 convert ----------------------------
__global__ void wconv_kernel(const float* __restrict__ W,
                             __half* __restrict__ hi, int taps, int K) {
    int i = blockIdx.x * blockDim.x + threadIdx.x;
    int total = taps * 128 * K;
    if (i >= total) return;
    int kk = i % K;
    int t2 = i / K;
    int n = t2 & 127;
    int tap = t2 >> 7;
    float v = __ldg(W + ((size_t)tap * K + kk) * 128 + n);
    hi[i] = __float2half_rn(v);
}

// ---------------- prep: feats fp16 convert (vector) ---------------------------
__global__ void xconv_kernel(const float4* __restrict__ X,
                             uint2* __restrict__ hi, long long n4) {
    long long i = (long long)blockIdx.x * blockDim.x + threadIdx.x;
    if (i >= n4) return;
    float4 v = X[i];
    __half2 h01 = __halves2half2(__float2half_rn(v.x), __float2half_rn(v.y));
    __half2 h23 = __halves2half2(__float2half_rn(v.z), __float2half_rn(v.w));
    hi[i] = make_uint2(*(uint32_t*)&h01, *(uint32_t*)&h23);
}

// ---------------- BN finalize from fused partials (parallel) ------------------
__device__ __forceinline__ void finalize_body(const float* g, const float* b,
                                              int slot, int pslot) {
    __shared__ float ss[8][COUT];
    __shared__ float sq[8][COUT];
    const int col = threadIdx.x & (COUT - 1);
    const int chunk = threadIdx.x >> 7;     // 0..7
    const int beg = chunk * 196;
    const int end = (chunk == 7) ? NPART : (beg + 196);
    float s0 = 0.f, s1 = 0.f, q0 = 0.f, q1 = 0.f;
    int i = beg;
    for (; i + 1 < end; i += 2) {
        s0 += g_psum[pslot][i][col];
        q0 += g_psq[pslot][i][col];
        s1 += g_psum[pslot][i + 1][col];
        q1 += g_psq[pslot][i + 1][col];
    }
    for (; i < end; i++) {
        s0 += g_psum[pslot][i][col];
        q0 += g_psq[pslot][i][col];
    }
    ss[chunk][col] = s0 + s1;
    sq[chunk][col] = q0 + q1;
    __syncthreads();
    if (chunk == 0) {
        float s = 0.f, q = 0.f;
#pragma unroll
        for (int c = 0; c < 8; c++) { s += ss[c][col]; q += sq[c][col]; }
        float mean = s * (1.0f / NROWS);
        float var = q * (1.0f / NROWS) - mean * mean;
        float inv = g[col] * rsqrtf(var + EPSBN);
        g_inv[slot][col] = inv;
        g_shift[slot][col] = b[col] - mean * inv;
    }
}

__global__ void finalize_kernel(const float* __restrict__ g,
                                const float* __restrict__ b, int slot, int pslot) {
    finalize_body(g, b, slot, pslot);
}

// fused: block 0 -> BN2 (slot 1, pslot 0); block 1 -> BNskip (slot 2, pslot 1)
__global__ void finalize2_kernel(const float* __restrict__ g2,
                                 const float* __restrict__ b2,
                                 const float* __restrict__ gsk,
                                 const float* __restrict__ bsk) {
    if (blockIdx.x == 0) finalize_body(g2, b2, 1, 0);
    else                 finalize_body(gsk, bsk, 2, 1);
}

// ---------------- BN apply (slot 0) on fp16 hpre -> fp16 hh -------------------
__global__ void bnconv_kernel(const uint2* __restrict__ X,
                              uint2* __restrict__ hi) {
    long long i = (long long)blockIdx.x * blockDim.x + threadIdx.x;
    const long long total = (long long)NROWS * COUT / 4;
    if (i >= total) return;
    int c4 = (int)(i & (COUT / 4 - 1)) * 4;
    uint2 raw = X[i];
    __half2 a = *(__half2*)&raw.x;
    __half2 bq = *(__half2*)&raw.y;
    float x0 = __low2float(a), x1 = __high2float(a);
    float x2 = __low2float(bq), x3 = __high2float(bq);
    x0 = x0 * g_inv[0][c4 + 0] + g_shift[0][c4 + 0];
    x1 = x1 * g_inv[0][c4 + 1] + g_shift[0][c4 + 1];
    x2 = x2 * g_inv[0][c4 + 2] + g_shift[0][c4 + 2];
    x3 = x3 * g_inv[0][c4 + 3] + g_shift[0][c4 + 3];
    __half2 h01 = __floats2half2_rn(x0, x1);
    __half2 h23 = __floats2half2_rn(x2, x3);
    hi[i] = make_uint2(*(uint32_t*)&h01, *(uint32_t*)&h23);
}

// ---------------- final: relu(bn(res) + bn(skip)), fp16 in / fp32 out --------
__global__ void final_kernel(float4* __restrict__ out) {
    long long i = (long long)blockIdx.x * blockDim.x + threadIdx.x;
    const long long total = (long long)NROWS * COUT / 4;
    if (i >= total) return;
    int c4 = (int)(i & (COUT / 4 - 1)) * 4;
    uint2 rraw = ((const uint2*)g_respre)[i];
    uint2 sraw = ((const uint2*)g_skippre)[i];
    __half2 r01 = *(__half2*)&rraw.x, r23 = *(__half2*)&rraw.y;
    __half2 s01 = *(__half2*)&sraw.x, s23 = *(__half2*)&sraw.y;
    float r0 = __low2float(r01), r1 = __high2float(r01);
    float r2 = __low2float(r23), r3 = __high2float(r23);
    float s0 = __low2float(s01), s1 = __high2float(s01);
    float s2 = __low2float(s23), s3 = __high2float(s23);
    float4 o;
    o.x = fmaxf(r0 * g_inv[1][c4 + 0] + g_shift[1][c4 + 0] +
                s0 * g_inv[2][c4 + 0] + g_shift[2][c4 + 0], 0.f);
    o.y = fmaxf(r1 * g_inv[1][c4 + 1] + g_shift[1][c4 + 1] +
                s1 * g_inv[2][c4 + 1] + g_shift[2][c4 + 1], 0.f);
    o.z = fmaxf(r2 * g_inv[1][c4 + 2] + g_shift[1][c4 + 2] +
                s2 * g_inv[2][c4 + 2] + g_shift[2][c4 + 2], 0.f);
    o.w = fmaxf(r3 * g_inv[1][c4 + 3] + g_shift[1][c4 + 3] +
                s3 * g_inv[2][c4 + 3] + g_shift[2][c4 + 3], 0.f);
    out[i] = o;
}

// ---------------- launch ------------------------------------------------------
extern "C" void kernel_launch(void* const* d_in, const int* in_sizes, int n_in,
                              void* d_out, int out_size) {
    const float* feats = (const float*)d_in[0];
    const int*   nbr   = (const int*)d_in[1];
    const float* W1    = (const float*)d_in[2];
    const float* g1    = (const float*)d_in[3];
    const float* b1    = (const float*)d_in[4];
    const float* W2    = (const float*)d_in[5];
    const float* g2    = (const float*)d_in[6];
    const float* b2    = (const float*)d_in[7];
    const float* Wsk   = (const float*)d_in[8];
    const float* gsk   = (const float*)d_in[9];
    const float* bsk   = (const float*)d_in[10];
    float* out = (float*)d_out;

    __half *hpre, *respre, *skippre;
    __half *fh, *hh, *w1h, *w2h, *wskh;
    cudaGetSymbolAddress((void**)&hpre, g_hpre);
    cudaGetSymbolAddress((void**)&respre, g_respre);
    cudaGetSymbolAddress((void**)&skippre, g_skippre);
    cudaGetSymbolAddress((void**)&fh, g_fh);
    cudaGetSymbolAddress((void**)&hh, g_hh);
    cudaGetSymbolAddress((void**)&w1h, g_w1h);
    cudaGetSymbolAddress((void**)&w2h, g_w2h);
    cudaGetSymbolAddress((void**)&wskh, g_wskh);

    const int SMEM_BYTES = NSTAGE * STAGE_B;  // 65536
    cudaFuncSetAttribute(mma_conv_kernel<true>,
                         cudaFuncAttributeMaxDynamicSharedMemorySize, SMEM_BYTES);
    cudaFuncSetAttribute(mma_conv_kernel<false>,
                         cudaFuncAttributeMaxDynamicSharedMemorySize, SMEM_BYTES);

    const int grid = NPART;  // 1563
    const long long total4 = (long long)NROWS * COUT / 4;
    const int egrid = (int)((total4 + 255) / 256);
    const long long f4 = (long long)NROWS * CIN1 / 4;

    // ---- prep (ordered so launch index 3 == conv1, which ncu captures)
    wconv_kernel<<<(NTAPS * 128 * CIN1 + 255) / 256, 256>>>(W1, w1h, NTAPS, CIN1);
    xconv_kernel<<<(int)((f4 + 255) / 256), 256>>>((const float4*)feats,
                                                   (uint2*)fh, f4);
    wconv_kernel<<<(NTAPS * 128 * COUT + 255) / 256, 256>>>(W2, w2h, NTAPS, COUT);

    // ---- conv1: 27 taps, K=64  (launch index 3 -> profiled); stats -> pslot 0
    mma_conv_kernel<true><<<grid, 256, SMEM_BYTES>>>(fh, nbr, w1h, hpre,
                                                     NTAPS, CIN1, 1, 0);

    // ---- skip branch; stats -> pslot 1
    wconv_kernel<<<(128 * CIN1 + 255) / 256, 256>>>(Wsk, wskh, 1, CIN1);
    mma_conv_kernel<false><<<grid, 256, SMEM_BYTES>>>(fh, nullptr, wskh, skippre,
                                                      1, CIN1, 1, 1);

    // ---- BN1 finalize (parallel) + fused apply+convert
    finalize_kernel<<<1, 1024>>>(g1, b1, 0, 0);
    bnconv_kernel<<<egrid, 256>>>((const uint2*)hpre, (uint2*)hh);
    // ---- conv2: 27 taps, K=128; stats -> pslot 0
    mma_conv_kernel<true><<<grid, 256, SMEM_BYTES>>>(hh, nbr, w2h, respre,
                                                     NTAPS, COUT, 2, 0);
    // ---- BN2 + BNskip finalize (fused into one launch)
    finalize2_kernel<<<2, 1024>>>(g2, b2, gsk, bsk);
    // ---- out = relu(bn(res) + bn(skip))
    final_kernel<<<egrid, 256>>>((float4*)out);
}